// round 8
// baseline (speedup 1.0000x reference)
#include <cuda_runtime.h>
#include <math.h>

#define NCH 256
#define TW 16
#define TH 4
#define OCT 64
#define CB 16
#define WPAD 68   // padded oc dim for weight smem; tap stride 272B (16B-aligned)
#define IRS2 18   // input row stride in float2 (144B, 16B-aligned)

#define SW_FLOATS (CB*9*WPAD)                  // 9792 floats = 39168 B
#define SW_BYTES  (SW_FLOATS*4)
#define SIN_BYTES (CB*(TH+2)*IRS2*8)           // 13824 B
#define SMEM_TOTAL (SW_BYTES + SIN_BYTES)      // 52992 B

// Scratch (static device globals; allocation is forbidden)
__device__ float g_buf0[8u*256u*64u*64u];   // 33.5 MB
__device__ float g_buf1[8u*256u*64u*64u];   // 33.5 MB
__device__ float g_head[8u*720u*64u*64u];   // 94.4 MB

typedef unsigned long long ull;

// packed f32x2 ops (Blackwell FFMA2 path — ptxas never emits from C++)
#define FMA2(D, A, B) asm("fma.rn.f32x2 %0, %1, %2, %0;" : "+l"(D) : "l"(A), "l"(B))
#define ADD2(D, A, B) asm("add.rn.f32x2 %0, %1, %2;" : "=l"(D) : "l"(A), "l"(B))
// D = A - B  via  A + (B ^ signmask)  (IEEE-identical to subtraction)
#define NSUB2(D, A, B) do { ull _nb; \
    asm("xor.b64 %0, %1, 0x8000000080000000;" : "=l"(_nb) : "l"(B)); \
    ADD2(D, A, _nb); } while(0)

__device__ __forceinline__ float plo(ull v){ return __uint_as_float((unsigned)v); }
__device__ __forceinline__ float phi(ull v){ return __uint_as_float((unsigned)(v>>32)); }

// One input channel (9 taps), packed: ACC[p][i] accumulates oc-pair p, pixel i.
// Inputs come pre-duplicated (v,v) from smem; weights pre-paired in smem.
#define CHANNEL9P(ACC, CI) \
    _Pragma("unroll") \
    for (int ky = 0; ky < 3; ky++) { \
        const ulonglong2* ib = (const ulonglong2*)(s_in2 + ((CI)*(TH+2) + py+ky)*IRS2 + px); \
        const ulonglong2 p0 = ib[0], p1 = ib[1], p2 = ib[2]; /* (a0,a0)..(a5,a5) */ \
        { const ulonglong2 wv = *(const ulonglong2*)&s_w[((CI)*9 + ky*3 + 0)*WPAD + (og<<2)]; \
          FMA2(ACC[0][0], wv.x, p0.x); FMA2(ACC[0][1], wv.x, p0.y); FMA2(ACC[0][2], wv.x, p1.x); FMA2(ACC[0][3], wv.x, p1.y); \
          FMA2(ACC[1][0], wv.y, p0.x); FMA2(ACC[1][1], wv.y, p0.y); FMA2(ACC[1][2], wv.y, p1.x); FMA2(ACC[1][3], wv.y, p1.y); } \
        { const ulonglong2 wv = *(const ulonglong2*)&s_w[((CI)*9 + ky*3 + 1)*WPAD + (og<<2)]; \
          FMA2(ACC[0][0], wv.x, p0.y); FMA2(ACC[0][1], wv.x, p1.x); FMA2(ACC[0][2], wv.x, p1.y); FMA2(ACC[0][3], wv.x, p2.x); \
          FMA2(ACC[1][0], wv.y, p0.y); FMA2(ACC[1][1], wv.y, p1.x); FMA2(ACC[1][2], wv.y, p1.y); FMA2(ACC[1][3], wv.y, p2.x); } \
        { const ulonglong2 wv = *(const ulonglong2*)&s_w[((CI)*9 + ky*3 + 2)*WPAD + (og<<2)]; \
          FMA2(ACC[0][0], wv.x, p1.x); FMA2(ACC[0][1], wv.x, p1.y); FMA2(ACC[0][2], wv.x, p2.x); FMA2(ACC[0][3], wv.x, p2.y); \
          FMA2(ACC[1][0], wv.y, p1.x); FMA2(ACC[1][1], wv.y, p1.y); FMA2(ACC[1][2], wv.y, p2.x); FMA2(ACC[1][3], wv.y, p2.y); } \
    }

// ---------------------------------------------------------------------------
// 3x3 SAME conv, C_in=256, OC generic, optional ReLU. Packed-f32x2 inner loop.
// Block: 256 threads -> [64 oc x 64 px]; thread: 2 oc-pairs x 4 px (packed).
// KAHAN=true (cls): compensated 4-channel folds (class_id argmax tie-safety).
// ---------------------------------------------------------------------------
template<bool KAHAN>
__global__ __launch_bounds__(256) void conv3x3_k(
    const float* __restrict__ in, const float* __restrict__ wt,
    const float* __restrict__ bias, float* __restrict__ out,
    int OC, int H, int W, int tilesX, int relu)
{
    extern __shared__ __align__(16) unsigned char smem_raw[];
    float*  s_w   = (float*)smem_raw;                     // [CB*9*WPAD]
    float2* s_in2 = (float2*)(smem_raw + SW_BYTES);       // [CB][TH+2][IRS2], (v,v)

    const int t   = threadIdx.x;
    const int tX  = blockIdx.x % tilesX;
    const int tY  = blockIdx.x / tilesX;
    const int oc0 = blockIdx.y * OCT;
    const int b   = blockIdx.z;
    const int og  = t & 15;
    const int pg  = t >> 4;
    const int px  = (pg & 3) << 2;
    const int py  = pg >> 2;
    const int gx0 = tX * TW, gy0 = tY * TH;

    // weight staging: 4 threads per oc, 9 x LDG.128 each
    const int w_oc = t >> 2;
    const int w_q  = t & 3;
    const int w_goc = oc0 + w_oc;
    const bool w_ok = (w_goc < OC);
    const float* wbase = wt + (size_t)(w_ok ? w_goc : 0) * (NCH*9);

    ull acc[2][4], cmp[2][4];
    #pragma unroll
    for (int p = 0; p < 2; p++)
        #pragma unroll
        for (int i = 0; i < 4; i++) { acc[p][i] = 0ull; cmp[p][i] = 0ull; }

    const float* inb = in + (size_t)b * NCH * H * W;

    for (int cb = 0; cb < NCH; cb += CB) {
        __syncthreads();
        // ---- stage input tile, duplicated (v,v), halo zero-padded ----
        #pragma unroll 2
        for (int i = t; i < CB*(TH+2)*(TW+2); i += 256) {
            int ci  = i / ((TH+2)*(TW+2));
            int rem = i - ci*((TH+2)*(TW+2));
            int r   = rem / (TW+2);
            int c   = rem - r*(TW+2);
            int gy  = gy0 + r - 1;
            int gx  = gx0 + c - 1;
            float v = 0.f;
            if ((unsigned)gy < (unsigned)H && (unsigned)gx < (unsigned)W)
                v = inb[((size_t)(cb+ci)*H + gy)*W + gx];
            s_in2[(ci*(TH+2) + r)*IRS2 + c] = make_float2(v, v);
        }
        // ---- stage weights: s_w[(ci*9+tap)*WPAD + oc] ----
        {
            const float* wp = wbase + (size_t)cb*9;
            #pragma unroll
            for (int k = 0; k < 9; k++) {
                int j0 = w_q*4 + k*16;
                float4 wv = make_float4(0.f, 0.f, 0.f, 0.f);
                if (w_ok) wv = *(const float4*)&wp[j0];
                s_w[(j0+0)*WPAD + w_oc] = wv.x;
                s_w[(j0+1)*WPAD + w_oc] = wv.y;
                s_w[(j0+2)*WPAD + w_oc] = wv.z;
                s_w[(j0+3)*WPAD + w_oc] = wv.w;
            }
        }
        __syncthreads();

        if (KAHAN) {
            #pragma unroll 1
            for (int cig = 0; cig < CB; cig += 4) {
                ull tt[2][4];
                #pragma unroll
                for (int p = 0; p < 2; p++)
                    #pragma unroll
                    for (int i = 0; i < 4; i++) tt[p][i] = 0ull;

                #pragma unroll
                for (int cc = 0; cc < 4; cc++) {
                    const int ci = cig + cc;
                    CHANNEL9P(tt, ci)
                }
                // compensated fold (per packed lane, IEEE-identical to scalar)
                #pragma unroll
                for (int p = 0; p < 2; p++) {
                    #pragma unroll
                    for (int i = 0; i < 4; i++) {
                        ull y, s, d;
                        NSUB2(y, tt[p][i], cmp[p][i]);
                        ADD2(s, acc[p][i], y);
                        NSUB2(d, s, acc[p][i]);
                        NSUB2(cmp[p][i], d, y);
                        acc[p][i] = s;
                    }
                }
            }
        } else {
            #pragma unroll 4
            for (int ci = 0; ci < CB; ci++) {
                CHANNEL9P(acc, ci)
            }
        }
    }

    int gy = gy0 + py;
    if (gy >= H) return;
    #pragma unroll
    for (int p = 0; p < 2; p++) {
        #pragma unroll
        for (int half = 0; half < 2; half++) {
            int goc = oc0 + og*4 + p*2 + half;
            if (goc >= OC) continue;
            float bv = bias[goc];
            #pragma unroll
            for (int i = 0; i < 4; i++) {
                int gx = gx0 + px + i;
                if (gx >= W) continue;
                float a = half ? phi(acc[p][i]) : plo(acc[p][i]);
                float v;
                if (KAHAN) {
                    float c = half ? phi(cmp[p][i]) : plo(cmp[p][i]);
                    v = (a - c) + bv;
                } else {
                    v = a + bv;
                }
                if (relu) v = fmaxf(v, 0.f);
                out[((size_t)b*OC + goc)*H*W + (size_t)gy*W + gx] = v;
            }
        }
    }
}

// ---------------------------------------------------------------------------
// cls epilogue: head [B,720,H,W] -> scores + class_id (argmax on logits).
// ---------------------------------------------------------------------------
__global__ void cls_reduce_k(const float* __restrict__ head,
                             float* __restrict__ scores, float* __restrict__ cls_id,
                             int H, int W, int Aoff, int Atot, int total)
{
    int idx = blockIdx.x * blockDim.x + threadIdx.x;
    if (idx >= total) return;
    int HW  = H * W;
    int pos = idx % HW;
    int tmp = idx / HW;
    int a   = tmp % 9;
    int b   = tmp / 9;
    const float* p = head + ((size_t)b*720 + (size_t)a*80) * HW + pos;
    float best = p[0];
    int   bi   = 0;
    #pragma unroll 4
    for (int k = 1; k < 80; k++) {
        float v = p[(size_t)k * HW];
        if (v > best) { best = v; bi = k; }
    }
    size_t o = (size_t)b*Atot + Aoff + (size_t)pos*9 + a;
    scores[o] = 1.f / (1.f + expf(-best));
    cls_id[o] = (float)bi;
}

// ---------------------------------------------------------------------------
// reg epilogue: head [B,36,H,W] -> decoded boxes, analytic anchors.
// ---------------------------------------------------------------------------
__global__ void reg_decode_k(const float* __restrict__ head, float* __restrict__ boxes,
                             int H, int W, int stride, int Aoff, int Atot, int total)
{
    int idx = blockIdx.x * blockDim.x + threadIdx.x;
    if (idx >= total) return;
    int HW  = H * W;
    int pos = idx % HW;
    int tmp = idx / HW;
    int a   = tmp % 9;
    int b   = tmp / 9;
    int x   = pos % W, y = pos / W;

    const float* p = head + ((size_t)b*36 + (size_t)a*4) * HW + pos;
    float d0 = p[0], d1 = p[HW], d2 = p[2*(size_t)HW], d3 = p[3*(size_t)HW];

    float s     = (float)stride;
    int   ridx  = a / 3, sidx = a - ridx*3;
    float ratio = (ridx == 0) ? 0.5f : ((ridx == 1) ? 1.f : 2.f);
    float scale = (sidx == 0) ? 1.f : ((sidx == 1) ? 1.2599210498948732f : 1.5874010519681994f);
    float w0 = 4.f * s * scale;
    float aw = w0 * rsqrtf(ratio);
    float ah = aw * ratio;
    float cx = (x + 0.5f) * s;
    float cy = (y + 0.5f) * s;

    float pcx = cx + d0 * 0.1f * aw;
    float pcy = cy + d1 * 0.1f * ah;
    float pw  = expf(d2 * 0.2f) * aw;
    float ph  = expf(d3 * 0.2f) * ah;

    float4 out4 = make_float4(pcx - 0.5f*pw, pcy - 0.5f*ph, pcx + 0.5f*pw, pcy + 0.5f*ph);
    size_t o = ((size_t)b*Atot + Aoff + (size_t)pos*9 + a);
    *(float4*)&boxes[o*4] = out4;
}

// ---------------------------------------------------------------------------
extern "C" void kernel_launch(void* const* d_in, const int* in_sizes, int n_in,
                              void* d_out, int out_size)
{
    static const int HS[5] = {64, 32, 16, 8, 4};
    static const int SS[5] = {8, 16, 32, 64, 128};

    // dynamic smem opt-in (no allocation; capture-legal host API)
    cudaFuncSetAttribute(conv3x3_k<true>,  cudaFuncAttributeMaxDynamicSharedMemorySize, SMEM_TOTAL);
    cudaFuncSetAttribute(conv3x3_k<false>, cudaFuncAttributeMaxDynamicSharedMemorySize, SMEM_TOTAL);

    const float* feat[5];
    const float *cw[5], *cbv[5], *rw[5], *rbv[5];
    for (int l = 0; l < 5; l++) feat[l] = (const float*)d_in[l];
    for (int i = 0; i < 5; i++) {
        cw[i]  = (const float*)d_in[5  + 2*i];
        cbv[i] = (const float*)d_in[6  + 2*i];
        rw[i]  = (const float*)d_in[15 + 2*i];
        rbv[i] = (const float*)d_in[16 + 2*i];
    }
    int B = in_sizes[0] / (256 * 64 * 64);

    float *buf0, *buf1, *headb;
    cudaGetSymbolAddress((void**)&buf0,  g_buf0);
    cudaGetSymbolAddress((void**)&buf1,  g_buf1);
    cudaGetSymbolAddress((void**)&headb, g_head);
    float* bufs[2] = {buf0, buf1};

    int Aoff[5], Atot = 0;
    for (int l = 0; l < 5; l++) { Aoff[l] = Atot; Atot += HS[l]*HS[l]*9; }

    float* out        = (float*)d_out;
    float* out_scores = out;
    float* out_cls    = out + (size_t)B * Atot;
    float* out_boxes  = out + (size_t)2 * B * Atot;

    for (int l = 0; l < 5; l++) {
        int H = HS[l], W = HS[l];
        int tilesX = (W + TW - 1) / TW;
        int tilesY = (H + TH - 1) / TH;
        dim3 grid(tilesX * tilesY, 4, B);
        dim3 gridCls(tilesX * tilesY, (720 + OCT - 1) / OCT, B);
        dim3 gridReg(tilesX * tilesY, 1, B);
        int total = B * 9 * H * W;
        int rblk  = (total + 255) / 256;

        // --- cls tower (compensated) ---
        const float* x = feat[l];
        for (int i = 0; i < 4; i++) {
            conv3x3_k<true><<<grid, 256, SMEM_TOTAL>>>(x, cw[i], cbv[i], bufs[i & 1], 256, H, W, tilesX, 1);
            x = bufs[i & 1];
        }
        conv3x3_k<true><<<gridCls, 256, SMEM_TOTAL>>>(x, cw[4], cbv[4], headb, 720, H, W, tilesX, 0);
        cls_reduce_k<<<rblk, 256>>>(headb, out_scores, out_cls, H, W, Aoff[l], Atot, total);

        // --- reg tower (plain) ---
        x = feat[l];
        for (int i = 0; i < 4; i++) {
            conv3x3_k<false><<<grid, 256, SMEM_TOTAL>>>(x, rw[i], rbv[i], bufs[i & 1], 256, H, W, tilesX, 1);
            x = bufs[i & 1];
        }
        conv3x3_k<false><<<gridReg, 256, SMEM_TOTAL>>>(x, rw[4], rbv[4], headb, 36, H, W, tilesX, 0);
        reg_decode_k<<<rblk, 256>>>(headb, out_boxes, H, W, SS[l], Aoff[l], Atot, total);
    }
    (void)n_in; (void)out_size;
}

// round 10
// speedup vs baseline: 1.2334x; 1.2334x over previous
#include <cuda_runtime.h>
#include <cuda_bf16.h>
#include <math.h>

#define NCH 256
#define TW 16
#define TH 4
#define OCT 64
#define CB 16
#define WPAD 68
#define IRS 20

__device__ float g_buf0[8u*256u*64u*64u];
__device__ float g_buf1[8u*256u*64u*64u];
__device__ float g_head[8u*720u*64u*64u];
__device__ unsigned g_actF[8u*256u*64u*64u];   // packed (bf16 hi | bf16 lo<<16)
__device__ unsigned g_act0[8u*256u*64u*64u];
__device__ unsigned g_act1[8u*256u*64u*64u];
__device__ unsigned g_wpack[4u*256u*2304u];    // packed reg weights [layer][oc][tap*256+c]

// ===================== scalar conv (R6, proven) =====================
#define FMA16(ACC, WV, A0, A1, A2, A3) \
    ACC[0][0] += (WV).x*(A0); ACC[0][1] += (WV).x*(A1); ACC[0][2] += (WV).x*(A2); ACC[0][3] += (WV).x*(A3); \
    ACC[1][0] += (WV).y*(A0); ACC[1][1] += (WV).y*(A1); ACC[1][2] += (WV).y*(A2); ACC[1][3] += (WV).y*(A3); \
    ACC[2][0] += (WV).z*(A0); ACC[2][1] += (WV).z*(A1); ACC[2][2] += (WV).z*(A2); ACC[2][3] += (WV).z*(A3); \
    ACC[3][0] += (WV).w*(A0); ACC[3][1] += (WV).w*(A1); ACC[3][2] += (WV).w*(A2); ACC[3][3] += (WV).w*(A3)

#define CHANNEL9(ACC, CI) \
    _Pragma("unroll") \
    for (int ky = 0; ky < 3; ky++) { \
        const float* irow = &s_in[CI][py+ky][px]; \
        const float4 va = *(const float4*)irow; \
        const float4 vb = *(const float4*)(irow + 4); \
        { const float4 wv = *(const float4*)&s_w[((CI)*9 + ky*3 + 0)*WPAD + (og<<2)]; \
          FMA16(ACC, wv, va.x, va.y, va.z, va.w); } \
        { const float4 wv = *(const float4*)&s_w[((CI)*9 + ky*3 + 1)*WPAD + (og<<2)]; \
          FMA16(ACC, wv, va.y, va.z, va.w, vb.x); } \
        { const float4 wv = *(const float4*)&s_w[((CI)*9 + ky*3 + 2)*WPAD + (og<<2)]; \
          FMA16(ACC, wv, va.z, va.w, vb.x, vb.y); } \
    }

template<bool KAHAN>
__global__ __launch_bounds__(256) void conv3x3_k(
    const float* __restrict__ in, const float* __restrict__ wt,
    const float* __restrict__ bias, float* __restrict__ out,
    int OC, int H, int W, int tilesX, int relu)
{
    __shared__ float s_in[CB][TH+2][IRS];
    __shared__ float s_w[CB*9*WPAD];

    const int t = threadIdx.x;
    const int tX = blockIdx.x % tilesX, tY = blockIdx.x / tilesX;
    const int oc0 = blockIdx.y * OCT, b = blockIdx.z;
    const int og = t & 15, pg = t >> 4;
    const int px = (pg & 3) << 2, py = pg >> 2;
    const int gx0 = tX * TW, gy0 = tY * TH;

    const int w_oc = t >> 2, w_q = t & 3;
    const int w_goc = oc0 + w_oc;
    const bool w_ok = (w_goc < OC);
    const float* wbase = wt + (size_t)(w_ok ? w_goc : 0) * (NCH*9);

    float acc[4][4], cmp[4][4];
    #pragma unroll
    for (int j = 0; j < 4; j++)
        #pragma unroll
        for (int i = 0; i < 4; i++) { acc[j][i] = 0.f; cmp[j][i] = 0.f; }

    const float* inb = in + (size_t)b * NCH * H * W;

    for (int cb = 0; cb < NCH; cb += CB) {
        __syncthreads();
        #pragma unroll 2
        for (int i = t; i < CB*(TH+2)*(TW+2); i += 256) {
            int ci = i / ((TH+2)*(TW+2));
            int rem = i - ci*((TH+2)*(TW+2));
            int r = rem / (TW+2), c = rem - r*(TW+2);
            int gy = gy0 + r - 1, gx = gx0 + c - 1;
            float v = 0.f;
            if ((unsigned)gy < (unsigned)H && (unsigned)gx < (unsigned)W)
                v = inb[((size_t)(cb+ci)*H + gy)*W + gx];
            s_in[ci][r][c] = v;
        }
        {
            const float* wp = wbase + (size_t)cb*9;
            #pragma unroll
            for (int kk = 0; kk < 9; kk++) {
                int j0 = w_q*4 + kk*16;
                float4 wv = make_float4(0.f,0.f,0.f,0.f);
                if (w_ok) wv = *(const float4*)&wp[j0];
                s_w[(j0+0)*WPAD + w_oc] = wv.x;
                s_w[(j0+1)*WPAD + w_oc] = wv.y;
                s_w[(j0+2)*WPAD + w_oc] = wv.z;
                s_w[(j0+3)*WPAD + w_oc] = wv.w;
            }
        }
        __syncthreads();

        if (KAHAN) {
            #pragma unroll 1
            for (int cig = 0; cig < CB; cig += 4) {
                float tt[4][4];
                #pragma unroll
                for (int j = 0; j < 4; j++)
                    #pragma unroll
                    for (int i = 0; i < 4; i++) tt[j][i] = 0.f;
                #pragma unroll
                for (int cc = 0; cc < 4; cc++) { const int ci = cig + cc; CHANNEL9(tt, ci) }
                #pragma unroll
                for (int j = 0; j < 4; j++)
                    #pragma unroll
                    for (int i = 0; i < 4; i++) {
                        float y = tt[j][i] - cmp[j][i];
                        float s = acc[j][i] + y;
                        cmp[j][i] = (s - acc[j][i]) - y;
                        acc[j][i] = s;
                    }
            }
        } else {
            #pragma unroll 4
            for (int ci = 0; ci < CB; ci++) { CHANNEL9(acc, ci) }
        }
    }

    int gy = gy0 + py;
    if (gy >= H) return;
    #pragma unroll
    for (int j = 0; j < 4; j++) {
        int goc = oc0 + og*4 + j;
        if (goc >= OC) continue;
        float bv = bias[goc];
        #pragma unroll
        for (int i = 0; i < 4; i++) {
            int gx = gx0 + px + i;
            if (gx >= W) continue;
            float v = KAHAN ? ((acc[j][i] - cmp[j][i]) + bv) : (acc[j][i] + bv);
            if (relu) v = fmaxf(v, 0.f);
            out[((size_t)b*OC + goc)*H*W + (size_t)gy*W + gx] = v;
        }
    }
}

// ===================== bf16 split pack helpers =====================
__device__ __forceinline__ unsigned pack_split(float v) {
    __nv_bfloat16 h = __float2bfloat16(v);
    __nv_bfloat16 l = __float2bfloat16(v - __bfloat162float(h));
    return (unsigned)__bfloat16_as_ushort(h) | ((unsigned)__bfloat16_as_ushort(l) << 16);
}
__global__ void split_act_k(const float* __restrict__ in, unsigned* __restrict__ op, int n) {
    int i = blockIdx.x * blockDim.x + threadIdx.x;
    if (i < n) op[i] = pack_split(in[i]);
}
__global__ void pack_w_k(const float* __restrict__ w, unsigned* __restrict__ op, int n) {
    int i = blockIdx.x * blockDim.x + threadIdx.x;
    if (i >= n) return;
    int oc = i / 2304, r = i - oc*2304, tap = r >> 8, c = r & 255;
    op[i] = pack_split(w[((size_t)oc*256 + c)*9 + tap]);
}

// ===================== warp-mma (sm_80 path, compiles at compute_100) ======
__device__ __forceinline__ unsigned smem_u32(const void* p) {
    unsigned a;
    asm("{ .reg .u64 t; cvta.to.shared.u64 t, %1; cvt.u32.u64 %0, t; }" : "=r"(a) : "l"(p));
    return a;
}
#define LDM_X4(R0,R1,R2,R3,ADDR) \
    asm volatile("ldmatrix.sync.aligned.m8n8.x4.shared.b16 {%0,%1,%2,%3}, [%4];" \
        : "=r"(R0),"=r"(R1),"=r"(R2),"=r"(R3) : "r"(ADDR))
#define MMA16816(D,A,B0,B1) \
    asm volatile("mma.sync.aligned.m16n8k16.row.col.f32.bf16.bf16.f32 " \
        "{%0,%1,%2,%3}, {%4,%5,%6,%7}, {%8,%9}, {%0,%1,%2,%3};" \
        : "+f"((D)[0]),"+f"((D)[1]),"+f"((D)[2]),"+f"((D)[3]) \
        : "r"((A)[0]),"r"((A)[1]),"r"((A)[2]),"r"((A)[3]),"r"(B0),"r"(B1))

// smem planes: [hiA | loA | hiB | loB], each [128 rows][72 bf16] (144B stride)
#define ROWB 144
#define PL   (128*ROWB)
#define MMA_SMEM (4*PL)   // 73728 B

// 3x3 SAME conv, Cin=256, OC=256, relu. bf16 hi/lo split, 3 products.
// Block: [128 px x 128 oc], 8 warps (warp = 32px x 64oc). 9 taps x 4 chunks.
__global__ __launch_bounds__(256) void conv_mma_k(
    const unsigned* __restrict__ actp, const unsigned* __restrict__ wp,
    const float* __restrict__ bias, float* __restrict__ outf,
    unsigned* __restrict__ outp, int klog, int HW)
{
    extern __shared__ __align__(16) unsigned char sm[];
    const unsigned smb = smem_u32(sm);
    const int t = threadIdx.x, lane = t & 31, wid = t >> 5;
    const int wm = wid & 3, wn = wid >> 2;
    const int m0 = blockIdx.x * 128, oc0 = blockIdx.y * 128;
    const int W = 1 << klog;

    float acc[2][8][4];
    #pragma unroll
    for (int mt = 0; mt < 2; mt++)
        #pragma unroll
        for (int nt = 0; nt < 8; nt++)
            #pragma unroll
            for (int k = 0; k < 4; k++) acc[mt][nt][k] = 0.f;

    // A staging geometry (px fixed per thread: t & 127)
    const int apx  = t & 127;
    const int am   = m0 + apx;
    const int ab   = am >> (2*klog);
    const int apos = am & (HW - 1);
    const int ay   = apos >> klog, ax = apos & (W - 1);
    const int ахh  = t >> 7;                 // 0/1 (A cp base)
    // B staging: oc = iter*8 + wid, cp = lane

    // ldmatrix base offsets (per warp/lane, constant)
    const unsigned a_rowoff = (unsigned)(wm*32 + (lane & 15)) * ROWB + ((lane >> 4) << 4);
    const unsigned b_rowoff = (unsigned)(wn*64 + (((lane >> 4) & 1) << 3) + (lane & 7)) * ROWB
                            + (((lane >> 3) & 1) << 4);

    #pragma unroll 1
    for (int tap = 0; tap < 9; tap++) {
        const int tky = tap / 3, tkx = tap - tky*3;
        const int gy = ay + tky - 1, gx = ax + tkx - 1;
        const bool aval = ((unsigned)gy < (unsigned)W) && ((unsigned)gx < (unsigned)W);
        const unsigned* abase = actp + (size_t)ab*256*HW + (aval ? ((gy << klog) + gx) : 0);
        const unsigned* bbase = wp + (size_t)oc0*2304 + tap*256;

        #pragma unroll 1
        for (int q = 0; q < 4; q++) {
            const int c0 = q * 64;
            __syncthreads();
            // ---- stage A (hi/lo planes) ----
            #pragma unroll
            for (int it = 0; it < 16; it++) {
                int cp = 2*it + ахh;                   // 0..31
                int c  = c0 + 2*cp;
                unsigned v0 = 0, v1 = 0;
                if (aval) {
                    v0 = abase[(size_t)c * HW];
                    v1 = abase[(size_t)(c+1) * HW];
                }
                *(unsigned*)(sm + (size_t)apx*ROWB + 4*cp)      = __byte_perm(v0, v1, 0x5410);
                *(unsigned*)(sm + PL + (size_t)apx*ROWB + 4*cp) = __byte_perm(v0, v1, 0x7632);
            }
            // ---- stage B ----
            #pragma unroll
            for (int it = 0; it < 16; it++) {
                int oc = it*8 + wid;                   // 0..127
                uint2 w2 = *(const uint2*)&bbase[(size_t)oc*2304 + c0 + 2*lane];
                *(unsigned*)(sm + 2*PL + (size_t)oc*ROWB + 4*lane) = __byte_perm(w2.x, w2.y, 0x5410);
                *(unsigned*)(sm + 3*PL + (size_t)oc*ROWB + 4*lane) = __byte_perm(w2.x, w2.y, 0x7632);
            }
            __syncthreads();

            // ---- mma: 4 k16 steps ----
            #pragma unroll
            for (int kc = 0; kc < 4; kc++) {
                unsigned ah[2][4], al[2][4];
                #pragma unroll
                for (int mt = 0; mt < 2; mt++) {
                    unsigned aaddr = smb + a_rowoff + (unsigned)mt*16*ROWB + (unsigned)kc*32;
                    LDM_X4(ah[mt][0], ah[mt][1], ah[mt][2], ah[mt][3], aaddr);
                    LDM_X4(al[mt][0], al[mt][1], al[mt][2], al[mt][3], aaddr + PL);
                }
                #pragma unroll
                for (int p = 0; p < 4; p++) {
                    unsigned bh[4], bl[4];
                    unsigned baddr = smb + 2*PL + b_rowoff + (unsigned)p*16*ROWB + (unsigned)kc*32;
                    LDM_X4(bh[0], bh[1], bh[2], bh[3], baddr);
                    LDM_X4(bl[0], bl[1], bl[2], bl[3], baddr + PL);
                    #pragma unroll
                    for (int mt = 0; mt < 2; mt++) {
                        MMA16816(acc[mt][2*p],   ah[mt], bh[0], bh[1]);
                        MMA16816(acc[mt][2*p],   ah[mt], bl[0], bl[1]);
                        MMA16816(acc[mt][2*p],   al[mt], bh[0], bh[1]);
                        MMA16816(acc[mt][2*p+1], ah[mt], bh[2], bh[3]);
                        MMA16816(acc[mt][2*p+1], ah[mt], bl[2], bl[3]);
                        MMA16816(acc[mt][2*p+1], al[mt], bh[2], bh[3]);
                    }
                }
            }
        }
    }

    // ---- epilogue: bias + relu, write fp32 + packed ----
    const int r  = lane >> 2;
    const int c2 = (lane & 3) * 2;
    #pragma unroll
    for (int mt = 0; mt < 2; mt++) {
        #pragma unroll
        for (int nt = 0; nt < 8; nt++) {
            int oc  = oc0 + wn*64 + nt*8 + c2;
            float b0 = bias[oc], b1 = bias[oc+1];
            #pragma unroll
            for (int half = 0; half < 2; half++) {
                int pxr = m0 + wm*32 + mt*16 + r + half*8;
                int bb  = pxr >> (2*klog);
                int pos = pxr & (HW - 1);
                size_t o0 = ((size_t)bb*256 + oc) * HW + pos;
                float v0 = fmaxf(acc[mt][nt][half*2+0] + b0, 0.f);
                float v1 = fmaxf(acc[mt][nt][half*2+1] + b1, 0.f);
                outf[o0]              = v0;
                outf[o0 + HW]         = v1;
                outp[o0]              = pack_split(v0);
                outp[o0 + HW]         = pack_split(v1);
            }
        }
    }
}

// ===================== epilogues =====================
__global__ void cls_reduce_k(const float* __restrict__ head,
                             float* __restrict__ scores, float* __restrict__ cls_id,
                             int H, int W, int Aoff, int Atot, int total)
{
    int idx = blockIdx.x * blockDim.x + threadIdx.x;
    if (idx >= total) return;
    int HW = H*W, pos = idx % HW, tmp = idx / HW, a = tmp % 9, b = tmp / 9;
    const float* p = head + ((size_t)b*720 + (size_t)a*80) * HW + pos;
    float best = p[0]; int bi = 0;
    #pragma unroll 4
    for (int k = 1; k < 80; k++) {
        float v = p[(size_t)k * HW];
        if (v > best) { best = v; bi = k; }
    }
    size_t o = (size_t)b*Atot + Aoff + (size_t)pos*9 + a;
    scores[o] = 1.f / (1.f + expf(-best));
    cls_id[o] = (float)bi;
}

__global__ void reg_decode_k(const float* __restrict__ head, float* __restrict__ boxes,
                             int H, int W, int stride, int Aoff, int Atot, int total)
{
    int idx = blockIdx.x * blockDim.x + threadIdx.x;
    if (idx >= total) return;
    int HW = H*W, pos = idx % HW, tmp = idx / HW, a = tmp % 9, b = tmp / 9;
    int x = pos % W, y = pos / W;
    const float* p = head + ((size_t)b*36 + (size_t)a*4) * HW + pos;
    float d0 = p[0], d1 = p[HW], d2 = p[2*(size_t)HW], d3 = p[3*(size_t)HW];
    float s = (float)stride;
    int ridx = a / 3, sidx = a - ridx*3;
    float ratio = (ridx == 0) ? 0.5f : ((ridx == 1) ? 1.f : 2.f);
    float scale = (sidx == 0) ? 1.f : ((sidx == 1) ? 1.2599210498948732f : 1.5874010519681994f);
    float aw = 4.f * s * scale * rsqrtf(ratio);
    float ah = aw * ratio;
    float cx = (x + 0.5f) * s, cy = (y + 0.5f) * s;
    float pcx = cx + d0 * 0.1f * aw;
    float pcy = cy + d1 * 0.1f * ah;
    float pw = expf(d2 * 0.2f) * aw;
    float ph = expf(d3 * 0.2f) * ah;
    float4 o4 = make_float4(pcx - 0.5f*pw, pcy - 0.5f*ph, pcx + 0.5f*pw, pcy + 0.5f*ph);
    size_t o = ((size_t)b*Atot + Aoff + (size_t)pos*9 + a);
    *(float4*)&boxes[o*4] = o4;
}

// ===========================================================================
extern "C" void kernel_launch(void* const* d_in, const int* in_sizes, int n_in,
                              void* d_out, int out_size)
{
    static const int HS[5] = {64, 32, 16, 8, 4};
    static const int KL[5] = {6, 5, 4, 3, 2};
    static const int SS[5] = {8, 16, 32, 64, 128};

    cudaFuncSetAttribute(conv_mma_k, cudaFuncAttributeMaxDynamicSharedMemorySize, MMA_SMEM);

    const float* feat[5];
    const float *cw[5], *cbv[5], *rw[5], *rbv[5];
    for (int l = 0; l < 5; l++) feat[l] = (const float*)d_in[l];
    for (int i = 0; i < 5; i++) {
        cw[i]  = (const float*)d_in[5  + 2*i];
        cbv[i] = (const float*)d_in[6  + 2*i];
        rw[i]  = (const float*)d_in[15 + 2*i];
        rbv[i] = (const float*)d_in[16 + 2*i];
    }
    int B = in_sizes[0] / (256 * 64 * 64);

    float *buf0, *buf1, *headb;
    unsigned *actF, *act0, *act1, *wpk;
    cudaGetSymbolAddress((void**)&buf0, g_buf0);
    cudaGetSymbolAddress((void**)&buf1, g_buf1);
    cudaGetSymbolAddress((void**)&headb, g_head);
    cudaGetSymbolAddress((void**)&actF, g_actF);
    cudaGetSymbolAddress((void**)&act0, g_act0);
    cudaGetSymbolAddress((void**)&act1, g_act1);
    cudaGetSymbolAddress((void**)&wpk, g_wpack);

    const int WN = 256*2304;
    for (int i = 0; i < 4; i++)
        pack_w_k<<<(WN + 255)/256, 256>>>(rw[i], wpk + (size_t)i*WN, WN);

    int Aoff[5], Atot = 0;
    for (int l = 0; l < 5; l++) { Aoff[l] = Atot; Atot += HS[l]*HS[l]*9; }

    float* out = (float*)d_out;
    float* out_scores = out;
    float* out_cls = out + (size_t)B * Atot;
    float* out_boxes = out + (size_t)2 * B * Atot;

    for (int l = 0; l < 5; l++) {
        int H = HS[l], W = HS[l], HW = H*W;
        int tilesX = (W + TW - 1) / TW, tilesY = (H + TH - 1) / TH;
        dim3 grid(tilesX * tilesY, 4, B);
        dim3 gridCls(tilesX * tilesY, (720 + OCT - 1) / OCT, B);
        dim3 gridReg(tilesX * tilesY, 1, B);
        int total = B * 9 * HW;
        int rblk = (total + 255) / 256;

        // --- cls tower (scalar + Kahan; class_id argmax is tie-sensitive) ---
        const float* x = feat[l];
        for (int i = 0; i < 4; i++) {
            conv3x3_k<true><<<grid, 256>>>(x, cw[i], cbv[i], (i&1)?buf1:buf0, 256, H, W, tilesX, 1);
            x = (i&1)?buf1:buf0;
        }
        conv3x3_k<true><<<gridCls, 256>>>(x, cw[4], cbv[4], headb, 720, H, W, tilesX, 0);
        cls_reduce_k<<<rblk, 256>>>(headb, out_scores, out_cls, H, W, Aoff[l], Atot, total);

        // --- reg tower: layers 0-3 on warp-mma (bf16 split) ---
        int n = B * 256 * HW;
        split_act_k<<<(n + 255)/256, 256>>>(feat[l], actF, n);
        dim3 gt(B * HW / 128, 2, 1);
        conv_mma_k<<<gt, 256, MMA_SMEM>>>(actF, wpk + 0*(size_t)WN, rbv[0], buf1, act0, KL[l], HW);
        conv_mma_k<<<gt, 256, MMA_SMEM>>>(act0, wpk + 1*(size_t)WN, rbv[1], buf1, act1, KL[l], HW);
        conv_mma_k<<<gt, 256, MMA_SMEM>>>(act1, wpk + 2*(size_t)WN, rbv[2], buf1, act0, KL[l], HW);
        conv_mma_k<<<gt, 256, MMA_SMEM>>>(act0, wpk + 3*(size_t)WN, rbv[3], buf0, act1, KL[l], HW);
        conv3x3_k<false><<<gridReg, 256>>>(buf0, rw[4], rbv[4], headb, 36, H, W, tilesX, 0);
        reg_decode_k<<<rblk, 256>>>(headb, out_boxes, H, W, SS[l], Aoff[l], Atot, total);
    }
    (void)n_in; (void)out_size;
}

// round 11
// speedup vs baseline: 1.2343x; 1.0007x over previous
#include <cuda_runtime.h>
#include <cuda_bf16.h>
#include <math.h>

#define NCH 256
#define TW 16
#define TH 4
#define OCT 64
#define CB 16
#define WPAD 68
#define IRS 20

__device__ float g_buf0[8u*256u*64u*64u];
__device__ float g_buf1[8u*256u*64u*64u];
__device__ float g_head[8u*720u*64u*64u];
__device__ unsigned g_actF[8u*256u*64u*64u];   // packed (bf16 hi | bf16 lo<<16)
__device__ unsigned g_act0[8u*256u*64u*64u];
__device__ unsigned g_act1[8u*256u*64u*64u];
__device__ unsigned g_wpack[4u*256u*2304u];    // packed reg weights [layer][oc][tap*256+c]

// ===================== scalar conv (R6, proven) =====================
#define FMA16(ACC, WV, A0, A1, A2, A3) \
    ACC[0][0] += (WV).x*(A0); ACC[0][1] += (WV).x*(A1); ACC[0][2] += (WV).x*(A2); ACC[0][3] += (WV).x*(A3); \
    ACC[1][0] += (WV).y*(A0); ACC[1][1] += (WV).y*(A1); ACC[1][2] += (WV).y*(A2); ACC[1][3] += (WV).y*(A3); \
    ACC[2][0] += (WV).z*(A0); ACC[2][1] += (WV).z*(A1); ACC[2][2] += (WV).z*(A2); ACC[2][3] += (WV).z*(A3); \
    ACC[3][0] += (WV).w*(A0); ACC[3][1] += (WV).w*(A1); ACC[3][2] += (WV).w*(A2); ACC[3][3] += (WV).w*(A3)

#define CHANNEL9(ACC, CI) \
    _Pragma("unroll") \
    for (int ky = 0; ky < 3; ky++) { \
        const float* irow = &s_in[CI][py+ky][px]; \
        const float4 va = *(const float4*)irow; \
        const float4 vb = *(const float4*)(irow + 4); \
        { const float4 wv = *(const float4*)&s_w[((CI)*9 + ky*3 + 0)*WPAD + (og<<2)]; \
          FMA16(ACC, wv, va.x, va.y, va.z, va.w); } \
        { const float4 wv = *(const float4*)&s_w[((CI)*9 + ky*3 + 1)*WPAD + (og<<2)]; \
          FMA16(ACC, wv, va.y, va.z, va.w, vb.x); } \
        { const float4 wv = *(const float4*)&s_w[((CI)*9 + ky*3 + 2)*WPAD + (og<<2)]; \
          FMA16(ACC, wv, va.z, va.w, vb.x, vb.y); } \
    }

template<bool KAHAN>
__global__ __launch_bounds__(256) void conv3x3_k(
    const float* __restrict__ in, const float* __restrict__ wt,
    const float* __restrict__ bias, float* __restrict__ out,
    int OC, int H, int W, int tilesX, int relu)
{
    __shared__ float s_in[CB][TH+2][IRS];
    __shared__ float s_w[CB*9*WPAD];

    const int t = threadIdx.x;
    const int tX = blockIdx.x % tilesX, tY = blockIdx.x / tilesX;
    const int oc0 = blockIdx.y * OCT, b = blockIdx.z;
    const int og = t & 15, pg = t >> 4;
    const int px = (pg & 3) << 2, py = pg >> 2;
    const int gx0 = tX * TW, gy0 = tY * TH;

    const int w_oc = t >> 2, w_q = t & 3;
    const int w_goc = oc0 + w_oc;
    const bool w_ok = (w_goc < OC);
    const float* wbase = wt + (size_t)(w_ok ? w_goc : 0) * (NCH*9);

    float acc[4][4], cmp[4][4];
    #pragma unroll
    for (int j = 0; j < 4; j++)
        #pragma unroll
        for (int i = 0; i < 4; i++) { acc[j][i] = 0.f; cmp[j][i] = 0.f; }

    const float* inb = in + (size_t)b * NCH * H * W;

    for (int cb = 0; cb < NCH; cb += CB) {
        __syncthreads();
        #pragma unroll 2
        for (int i = t; i < CB*(TH+2)*(TW+2); i += 256) {
            int ci = i / ((TH+2)*(TW+2));
            int rem = i - ci*((TH+2)*(TW+2));
            int r = rem / (TW+2), c = rem - r*(TW+2);
            int gy = gy0 + r - 1, gx = gx0 + c - 1;
            float v = 0.f;
            if ((unsigned)gy < (unsigned)H && (unsigned)gx < (unsigned)W)
                v = inb[((size_t)(cb+ci)*H + gy)*W + gx];
            s_in[ci][r][c] = v;
        }
        {
            const float* wp = wbase + (size_t)cb*9;
            #pragma unroll
            for (int kk = 0; kk < 9; kk++) {
                int j0 = w_q*4 + kk*16;
                float4 wv = make_float4(0.f,0.f,0.f,0.f);
                if (w_ok) wv = *(const float4*)&wp[j0];
                s_w[(j0+0)*WPAD + w_oc] = wv.x;
                s_w[(j0+1)*WPAD + w_oc] = wv.y;
                s_w[(j0+2)*WPAD + w_oc] = wv.z;
                s_w[(j0+3)*WPAD + w_oc] = wv.w;
            }
        }
        __syncthreads();

        if (KAHAN) {
            #pragma unroll 1
            for (int cig = 0; cig < CB; cig += 4) {
                float tt[4][4];
                #pragma unroll
                for (int j = 0; j < 4; j++)
                    #pragma unroll
                    for (int i = 0; i < 4; i++) tt[j][i] = 0.f;
                #pragma unroll
                for (int cc = 0; cc < 4; cc++) { const int ci = cig + cc; CHANNEL9(tt, ci) }
                #pragma unroll
                for (int j = 0; j < 4; j++)
                    #pragma unroll
                    for (int i = 0; i < 4; i++) {
                        float y = tt[j][i] - cmp[j][i];
                        float s = acc[j][i] + y;
                        cmp[j][i] = (s - acc[j][i]) - y;
                        acc[j][i] = s;
                    }
            }
        } else {
            #pragma unroll 4
            for (int ci = 0; ci < CB; ci++) { CHANNEL9(acc, ci) }
        }
    }

    int gy = gy0 + py;
    if (gy >= H) return;
    #pragma unroll
    for (int j = 0; j < 4; j++) {
        int goc = oc0 + og*4 + j;
        if (goc >= OC) continue;
        float bv = bias[goc];
        #pragma unroll
        for (int i = 0; i < 4; i++) {
            int gx = gx0 + px + i;
            if (gx >= W) continue;
            float v = KAHAN ? ((acc[j][i] - cmp[j][i]) + bv) : (acc[j][i] + bv);
            if (relu) v = fmaxf(v, 0.f);
            out[((size_t)b*OC + goc)*H*W + (size_t)gy*W + gx] = v;
        }
    }
}

// ===================== bf16 split pack helpers =====================
__device__ __forceinline__ unsigned pack_split(float v) {
    __nv_bfloat16 h = __float2bfloat16(v);
    __nv_bfloat16 l = __float2bfloat16(v - __bfloat162float(h));
    return (unsigned)__bfloat16_as_ushort(h) | ((unsigned)__bfloat16_as_ushort(l) << 16);
}
__global__ void split_act_k(const float* __restrict__ in, unsigned* __restrict__ op, int n) {
    int i = blockIdx.x * blockDim.x + threadIdx.x;
    if (i < n) op[i] = pack_split(in[i]);
}
__global__ void pack_w_k(const float* __restrict__ w, unsigned* __restrict__ op, int n) {
    int i = blockIdx.x * blockDim.x + threadIdx.x;
    if (i >= n) return;
    int oc = i / 2304, r = i - oc*2304, tap = r >> 8, c = r & 255;
    op[i] = pack_split(w[((size_t)oc*256 + c)*9 + tap]);
}

// ===================== warp-mma (sm_80 path, compiles at compute_100) ======
__device__ __forceinline__ unsigned smem_u32(const void* p) {
    unsigned a;
    asm("{ .reg .u64 t; cvta.to.shared.u64 t, %1; cvt.u32.u64 %0, t; }" : "=r"(a) : "l"(p));
    return a;
}
#define LDM_X4(R0,R1,R2,R3,ADDR) \
    asm volatile("ldmatrix.sync.aligned.m8n8.x4.shared.b16 {%0,%1,%2,%3}, [%4];" \
        : "=r"(R0),"=r"(R1),"=r"(R2),"=r"(R3) : "r"(ADDR))
#define MMA16816(D,A,B0,B1) \
    asm volatile("mma.sync.aligned.m16n8k16.row.col.f32.bf16.bf16.f32 " \
        "{%0,%1,%2,%3}, {%4,%5,%6,%7}, {%8,%9}, {%0,%1,%2,%3};" \
        : "+f"((D)[0]),"+f"((D)[1]),"+f"((D)[2]),"+f"((D)[3]) \
        : "r"((A)[0]),"r"((A)[1]),"r"((A)[2]),"r"((A)[3]),"r"(B0),"r"(B1))

// smem planes: [hiA | loA | hiB | loB], each [128 rows][72 bf16] (144B stride)
#define ROWB 144
#define PL   (128*ROWB)
#define MMA_SMEM (4*PL)   // 73728 B

// 3x3 SAME conv, Cin=256, OC=256, relu. bf16 hi/lo split, 3 products.
// Block: [128 px x 128 oc], 8 warps (warp = 32px x 64oc). 9 taps x 4 chunks.
__global__ __launch_bounds__(256) void conv_mma_k(
    const unsigned* __restrict__ actp, const unsigned* __restrict__ wp,
    const float* __restrict__ bias, float* __restrict__ outf,
    unsigned* __restrict__ outp, int klog, int HW)
{
    extern __shared__ __align__(16) unsigned char sm[];
    const unsigned smb = smem_u32(sm);
    const int t = threadIdx.x, lane = t & 31, wid = t >> 5;
    const int wm = wid & 3, wn = wid >> 2;
    const int m0 = blockIdx.x * 128, oc0 = blockIdx.y * 128;
    const int W = 1 << klog;

    float acc[2][8][4];
    #pragma unroll
    for (int mt = 0; mt < 2; mt++)
        #pragma unroll
        for (int nt = 0; nt < 8; nt++)
            #pragma unroll
            for (int k = 0; k < 4; k++) acc[mt][nt][k] = 0.f;

    // A staging geometry (px fixed per thread: t & 127)
    const int apx  = t & 127;
    const int am   = m0 + apx;
    const int ab   = am >> (2*klog);
    const int apos = am & (HW - 1);
    const int ay   = apos >> klog, ax = apos & (W - 1);
    const int ахh  = t >> 7;                 // 0/1 (A cp base)
    // B staging: oc = iter*8 + wid, cp = lane

    // ldmatrix base offsets (per warp/lane, constant)
    const unsigned a_rowoff = (unsigned)(wm*32 + (lane & 15)) * ROWB + ((lane >> 4) << 4);
    const unsigned b_rowoff = (unsigned)(wn*64 + (((lane >> 4) & 1) << 3) + (lane & 7)) * ROWB
                            + (((lane >> 3) & 1) << 4);

    #pragma unroll 1
    for (int tap = 0; tap < 9; tap++) {
        const int tky = tap / 3, tkx = tap - tky*3;
        const int gy = ay + tky - 1, gx = ax + tkx - 1;
        const bool aval = ((unsigned)gy < (unsigned)W) && ((unsigned)gx < (unsigned)W);
        const unsigned* abase = actp + (size_t)ab*256*HW + (aval ? ((gy << klog) + gx) : 0);
        const unsigned* bbase = wp + (size_t)oc0*2304 + tap*256;

        #pragma unroll 1
        for (int q = 0; q < 4; q++) {
            const int c0 = q * 64;
            __syncthreads();
            // ---- stage A (hi/lo planes) ----
            #pragma unroll
            for (int it = 0; it < 16; it++) {
                int cp = 2*it + ахh;                   // 0..31
                int c  = c0 + 2*cp;
                unsigned v0 = 0, v1 = 0;
                if (aval) {
                    v0 = abase[(size_t)c * HW];
                    v1 = abase[(size_t)(c+1) * HW];
                }
                *(unsigned*)(sm + (size_t)apx*ROWB + 4*cp)      = __byte_perm(v0, v1, 0x5410);
                *(unsigned*)(sm + PL + (size_t)apx*ROWB + 4*cp) = __byte_perm(v0, v1, 0x7632);
            }
            // ---- stage B ----
            #pragma unroll
            for (int it = 0; it < 16; it++) {
                int oc = it*8 + wid;                   // 0..127
                uint2 w2 = *(const uint2*)&bbase[(size_t)oc*2304 + c0 + 2*lane];
                *(unsigned*)(sm + 2*PL + (size_t)oc*ROWB + 4*lane) = __byte_perm(w2.x, w2.y, 0x5410);
                *(unsigned*)(sm + 3*PL + (size_t)oc*ROWB + 4*lane) = __byte_perm(w2.x, w2.y, 0x7632);
            }
            __syncthreads();

            // ---- mma: 4 k16 steps ----
            #pragma unroll
            for (int kc = 0; kc < 4; kc++) {
                unsigned ah[2][4], al[2][4];
                #pragma unroll
                for (int mt = 0; mt < 2; mt++) {
                    unsigned aaddr = smb + a_rowoff + (unsigned)mt*16*ROWB + (unsigned)kc*32;
                    LDM_X4(ah[mt][0], ah[mt][1], ah[mt][2], ah[mt][3], aaddr);
                    LDM_X4(al[mt][0], al[mt][1], al[mt][2], al[mt][3], aaddr + PL);
                }
                #pragma unroll
                for (int p = 0; p < 4; p++) {
                    unsigned bh[4], bl[4];
                    unsigned baddr = smb + 2*PL + b_rowoff + (unsigned)p*16*ROWB + (unsigned)kc*32;
                    LDM_X4(bh[0], bh[1], bh[2], bh[3], baddr);
                    LDM_X4(bl[0], bl[1], bl[2], bl[3], baddr + PL);
                    #pragma unroll
                    for (int mt = 0; mt < 2; mt++) {
                        MMA16816(acc[mt][2*p],   ah[mt], bh[0], bh[1]);
                        MMA16816(acc[mt][2*p],   ah[mt], bl[0], bl[1]);
                        MMA16816(acc[mt][2*p],   al[mt], bh[0], bh[1]);
                        MMA16816(acc[mt][2*p+1], ah[mt], bh[2], bh[3]);
                        MMA16816(acc[mt][2*p+1], ah[mt], bl[2], bl[3]);
                        MMA16816(acc[mt][2*p+1], al[mt], bh[2], bh[3]);
                    }
                }
            }
        }
    }

    // ---- epilogue: bias + relu, write fp32 + packed ----
    const int r  = lane >> 2;
    const int c2 = (lane & 3) * 2;
    #pragma unroll
    for (int mt = 0; mt < 2; mt++) {
        #pragma unroll
        for (int nt = 0; nt < 8; nt++) {
            int oc  = oc0 + wn*64 + nt*8 + c2;
            float b0 = bias[oc], b1 = bias[oc+1];
            #pragma unroll
            for (int half = 0; half < 2; half++) {
                int pxr = m0 + wm*32 + mt*16 + r + half*8;
                int bb  = pxr >> (2*klog);
                int pos = pxr & (HW - 1);
                size_t o0 = ((size_t)bb*256 + oc) * HW + pos;
                float v0 = fmaxf(acc[mt][nt][half*2+0] + b0, 0.f);
                float v1 = fmaxf(acc[mt][nt][half*2+1] + b1, 0.f);
                outf[o0]              = v0;
                outf[o0 + HW]         = v1;
                outp[o0]              = pack_split(v0);
                outp[o0 + HW]         = pack_split(v1);
            }
        }
    }
}

// ===================== epilogues =====================
__global__ void cls_reduce_k(const float* __restrict__ head,
                             float* __restrict__ scores, float* __restrict__ cls_id,
                             int H, int W, int Aoff, int Atot, int total)
{
    int idx = blockIdx.x * blockDim.x + threadIdx.x;
    if (idx >= total) return;
    int HW = H*W, pos = idx % HW, tmp = idx / HW, a = tmp % 9, b = tmp / 9;
    const float* p = head + ((size_t)b*720 + (size_t)a*80) * HW + pos;
    float best = p[0]; int bi = 0;
    #pragma unroll 4
    for (int k = 1; k < 80; k++) {
        float v = p[(size_t)k * HW];
        if (v > best) { best = v; bi = k; }
    }
    size_t o = (size_t)b*Atot + Aoff + (size_t)pos*9 + a;
    scores[o] = 1.f / (1.f + expf(-best));
    cls_id[o] = (float)bi;
}

__global__ void reg_decode_k(const float* __restrict__ head, float* __restrict__ boxes,
                             int H, int W, int stride, int Aoff, int Atot, int total)
{
    int idx = blockIdx.x * blockDim.x + threadIdx.x;
    if (idx >= total) return;
    int HW = H*W, pos = idx % HW, tmp = idx / HW, a = tmp % 9, b = tmp / 9;
    int x = pos % W, y = pos / W;
    const float* p = head + ((size_t)b*36 + (size_t)a*4) * HW + pos;
    float d0 = p[0], d1 = p[HW], d2 = p[2*(size_t)HW], d3 = p[3*(size_t)HW];
    float s = (float)stride;
    int ridx = a / 3, sidx = a - ridx*3;
    float ratio = (ridx == 0) ? 0.5f : ((ridx == 1) ? 1.f : 2.f);
    float scale = (sidx == 0) ? 1.f : ((sidx == 1) ? 1.2599210498948732f : 1.5874010519681994f);
    float aw = 4.f * s * scale * rsqrtf(ratio);
    float ah = aw * ratio;
    float cx = (x + 0.5f) * s, cy = (y + 0.5f) * s;
    float pcx = cx + d0 * 0.1f * aw;
    float pcy = cy + d1 * 0.1f * ah;
    float pw = expf(d2 * 0.2f) * aw;
    float ph = expf(d3 * 0.2f) * ah;
    float4 o4 = make_float4(pcx - 0.5f*pw, pcy - 0.5f*ph, pcx + 0.5f*pw, pcy + 0.5f*ph);
    size_t o = ((size_t)b*Atot + Aoff + (size_t)pos*9 + a);
    *(float4*)&boxes[o*4] = o4;
}

// ===========================================================================
extern "C" void kernel_launch(void* const* d_in, const int* in_sizes, int n_in,
                              void* d_out, int out_size)
{
    static const int HS[5] = {64, 32, 16, 8, 4};
    static const int KL[5] = {6, 5, 4, 3, 2};
    static const int SS[5] = {8, 16, 32, 64, 128};

    cudaFuncSetAttribute(conv_mma_k, cudaFuncAttributeMaxDynamicSharedMemorySize, MMA_SMEM);

    const float* feat[5];
    const float *cw[5], *cbv[5], *rw[5], *rbv[5];
    for (int l = 0; l < 5; l++) feat[l] = (const float*)d_in[l];
    for (int i = 0; i < 5; i++) {
        cw[i]  = (const float*)d_in[5  + 2*i];
        cbv[i] = (const float*)d_in[6  + 2*i];
        rw[i]  = (const float*)d_in[15 + 2*i];
        rbv[i] = (const float*)d_in[16 + 2*i];
    }
    int B = in_sizes[0] / (256 * 64 * 64);

    float *buf0, *buf1, *headb;
    unsigned *actF, *act0, *act1, *wpk;
    cudaGetSymbolAddress((void**)&buf0, g_buf0);
    cudaGetSymbolAddress((void**)&buf1, g_buf1);
    cudaGetSymbolAddress((void**)&headb, g_head);
    cudaGetSymbolAddress((void**)&actF, g_actF);
    cudaGetSymbolAddress((void**)&act0, g_act0);
    cudaGetSymbolAddress((void**)&act1, g_act1);
    cudaGetSymbolAddress((void**)&wpk, g_wpack);

    const int WN = 256*2304;
    for (int i = 0; i < 4; i++)
        pack_w_k<<<(WN + 255)/256, 256>>>(rw[i], wpk + (size_t)i*WN, WN);

    int Aoff[5], Atot = 0;
    for (int l = 0; l < 5; l++) { Aoff[l] = Atot; Atot += HS[l]*HS[l]*9; }

    float* out = (float*)d_out;
    float* out_scores = out;
    float* out_cls = out + (size_t)B * Atot;
    float* out_boxes = out + (size_t)2 * B * Atot;

    for (int l = 0; l < 5; l++) {
        int H = HS[l], W = HS[l], HW = H*W;
        int tilesX = (W + TW - 1) / TW, tilesY = (H + TH - 1) / TH;
        dim3 grid(tilesX * tilesY, 4, B);
        dim3 gridCls(tilesX * tilesY, (720 + OCT - 1) / OCT, B);
        dim3 gridReg(tilesX * tilesY, 1, B);
        int total = B * 9 * HW;
        int rblk = (total + 255) / 256;

        // --- cls tower (scalar + Kahan; class_id argmax is tie-sensitive) ---
        const float* x = feat[l];
        for (int i = 0; i < 4; i++) {
            conv3x3_k<true><<<grid, 256>>>(x, cw[i], cbv[i], (i&1)?buf1:buf0, 256, H, W, tilesX, 1);
            x = (i&1)?buf1:buf0;
        }
        conv3x3_k<true><<<gridCls, 256>>>(x, cw[4], cbv[4], headb, 720, H, W, tilesX, 0);
        cls_reduce_k<<<rblk, 256>>>(headb, out_scores, out_cls, H, W, Aoff[l], Atot, total);

        // --- reg tower: layers 0-3 on warp-mma (bf16 split) ---
        int n = B * 256 * HW;
        split_act_k<<<(n + 255)/256, 256>>>(feat[l], actF, n);
        dim3 gt(B * HW / 128, 2, 1);
        conv_mma_k<<<gt, 256, MMA_SMEM>>>(actF, wpk + 0*(size_t)WN, rbv[0], buf1, act0, KL[l], HW);
        conv_mma_k<<<gt, 256, MMA_SMEM>>>(act0, wpk + 1*(size_t)WN, rbv[1], buf1, act1, KL[l], HW);
        conv_mma_k<<<gt, 256, MMA_SMEM>>>(act1, wpk + 2*(size_t)WN, rbv[2], buf1, act0, KL[l], HW);
        conv_mma_k<<<gt, 256, MMA_SMEM>>>(act0, wpk + 3*(size_t)WN, rbv[3], buf0, act1, KL[l], HW);
        conv3x3_k<false><<<gridReg, 256>>>(buf0, rw[4], rbv[4], headb, 36, H, W, tilesX, 0);
        reg_decode_k<<<rblk, 256>>>(headb, out_boxes, H, W, SS[l], Aoff[l], Atot, total);
    }
    (void)n_in; (void)out_size;
}

// round 13
// speedup vs baseline: 1.3054x; 1.0576x over previous
#include <cuda_runtime.h>
#include <cuda_bf16.h>
#include <math.h>

#define NCH 256
#define TW 16
#define TH 4
#define OCT 64
#define CB 16
#define WPAD 68
#define IRS 20

// fp32 NCHW scratch + head
__device__ float g_buf0[8u*256u*64u*64u];
__device__ float g_buf1[8u*256u*64u*64u];
__device__ float g_head[8u*720u*64u*64u];
// NHWC bf16 hi/lo activation planes (ping-pong)
__device__ __nv_bfloat16 g_aH0[8u*4096u*256u];
__device__ __nv_bfloat16 g_aL0[8u*4096u*256u];
__device__ __nv_bfloat16 g_aH1[8u*4096u*256u];
__device__ __nv_bfloat16 g_aL1[8u*4096u*256u];
// packed reg weights: [layer][tap(9)][q(4)][plane(2)][oc(256)][ch(64)]
__device__ __nv_bfloat16 g_wB[4u*9u*4u*2u*256u*64u];

// ===================== scalar conv (R6, proven) =====================
#define FMA16(ACC, WV, A0, A1, A2, A3) \
    ACC[0][0] += (WV).x*(A0); ACC[0][1] += (WV).x*(A1); ACC[0][2] += (WV).x*(A2); ACC[0][3] += (WV).x*(A3); \
    ACC[1][0] += (WV).y*(A0); ACC[1][1] += (WV).y*(A1); ACC[1][2] += (WV).y*(A2); ACC[1][3] += (WV).y*(A3); \
    ACC[2][0] += (WV).z*(A0); ACC[2][1] += (WV).z*(A1); ACC[2][2] += (WV).z*(A2); ACC[2][3] += (WV).z*(A3); \
    ACC[3][0] += (WV).w*(A0); ACC[3][1] += (WV).w*(A1); ACC[3][2] += (WV).w*(A2); ACC[3][3] += (WV).w*(A3)

#define CHANNEL9(ACC, CI) \
    _Pragma("unroll") \
    for (int ky = 0; ky < 3; ky++) { \
        const float* irow = &s_in[CI][py+ky][px]; \
        const float4 va = *(const float4*)irow; \
        const float4 vb = *(const float4*)(irow + 4); \
        { const float4 wv = *(const float4*)&s_w[((CI)*9 + ky*3 + 0)*WPAD + (og<<2)]; \
          FMA16(ACC, wv, va.x, va.y, va.z, va.w); } \
        { const float4 wv = *(const float4*)&s_w[((CI)*9 + ky*3 + 1)*WPAD + (og<<2)]; \
          FMA16(ACC, wv, va.y, va.z, va.w, vb.x); } \
        { const float4 wv = *(const float4*)&s_w[((CI)*9 + ky*3 + 2)*WPAD + (og<<2)]; \
          FMA16(ACC, wv, va.z, va.w, vb.x, vb.y); } \
    }

template<bool KAHAN>
__global__ __launch_bounds__(256) void conv3x3_k(
    const float* __restrict__ in, const float* __restrict__ wt,
    const float* __restrict__ bias, float* __restrict__ out,
    int OC, int H, int W, int tilesX, int relu)
{
    __shared__ float s_in[CB][TH+2][IRS];
    __shared__ float s_w[CB*9*WPAD];

    const int t = threadIdx.x;
    const int tX = blockIdx.x % tilesX, tY = blockIdx.x / tilesX;
    const int oc0 = blockIdx.y * OCT, b = blockIdx.z;
    const int og = t & 15, pg = t >> 4;
    const int px = (pg & 3) << 2, py = pg >> 2;
    const int gx0 = tX * TW, gy0 = tY * TH;

    const int w_oc = t >> 2, w_q = t & 3;
    const int w_goc = oc0 + w_oc;
    const bool w_ok = (w_goc < OC);
    const float* wbase = wt + (size_t)(w_ok ? w_goc : 0) * (NCH*9);

    float acc[4][4], cmp[4][4];
    #pragma unroll
    for (int j = 0; j < 4; j++)
        #pragma unroll
        for (int i = 0; i < 4; i++) { acc[j][i] = 0.f; cmp[j][i] = 0.f; }

    const float* inb = in + (size_t)b * NCH * H * W;

    for (int cb = 0; cb < NCH; cb += CB) {
        __syncthreads();
        #pragma unroll 2
        for (int i = t; i < CB*(TH+2)*(TW+2); i += 256) {
            int ci = i / ((TH+2)*(TW+2));
            int rem = i - ci*((TH+2)*(TW+2));
            int r = rem / (TW+2), c = rem - r*(TW+2);
            int gy = gy0 + r - 1, gx = gx0 + c - 1;
            float v = 0.f;
            if ((unsigned)gy < (unsigned)H && (unsigned)gx < (unsigned)W)
                v = inb[((size_t)(cb+ci)*H + gy)*W + gx];
            s_in[ci][r][c] = v;
        }
        {
            const float* wp = wbase + (size_t)cb*9;
            #pragma unroll
            for (int kk = 0; kk < 9; kk++) {
                int j0 = w_q*4 + kk*16;
                float4 wv = make_float4(0.f,0.f,0.f,0.f);
                if (w_ok) wv = *(const float4*)&wp[j0];
                s_w[(j0+0)*WPAD + w_oc] = wv.x;
                s_w[(j0+1)*WPAD + w_oc] = wv.y;
                s_w[(j0+2)*WPAD + w_oc] = wv.z;
                s_w[(j0+3)*WPAD + w_oc] = wv.w;
            }
        }
        __syncthreads();

        if (KAHAN) {
            #pragma unroll 1
            for (int cig = 0; cig < CB; cig += 4) {
                float tt[4][4];
                #pragma unroll
                for (int j = 0; j < 4; j++)
                    #pragma unroll
                    for (int i = 0; i < 4; i++) tt[j][i] = 0.f;
                #pragma unroll
                for (int cc = 0; cc < 4; cc++) { const int ci = cig + cc; CHANNEL9(tt, ci) }
                #pragma unroll
                for (int j = 0; j < 4; j++)
                    #pragma unroll
                    for (int i = 0; i < 4; i++) {
                        float y = tt[j][i] - cmp[j][i];
                        float s = acc[j][i] + y;
                        cmp[j][i] = (s - acc[j][i]) - y;
                        acc[j][i] = s;
                    }
            }
        } else {
            #pragma unroll 4
            for (int ci = 0; ci < CB; ci++) { CHANNEL9(acc, ci) }
        }
    }

    int gy = gy0 + py;
    if (gy >= H) return;
    #pragma unroll
    for (int j = 0; j < 4; j++) {
        int goc = oc0 + og*4 + j;
        if (goc >= OC) continue;
        float bv = bias[goc];
        #pragma unroll
        for (int i = 0; i < 4; i++) {
            int gx = gx0 + px + i;
            if (gx >= W) continue;
            float v = KAHAN ? ((acc[j][i] - cmp[j][i]) + bv) : (acc[j][i] + bv);
            if (relu) v = fmaxf(v, 0.f);
            out[((size_t)b*OC + goc)*H*W + (size_t)gy*W + gx] = v;
        }
    }
}

// ===================== prep kernels =====================
// NCHW fp32 -> NHWC bf16 hi/lo planes (tiled transpose)
__global__ void split_nhwc_k(const float* __restrict__ in,
                             __nv_bfloat16* __restrict__ oH, __nv_bfloat16* __restrict__ oL,
                             int HW)
{
    __shared__ float tile[16][17];
    int pos0 = blockIdx.x * 16, c0 = blockIdx.y * 16, b = blockIdx.z;
    int tx = threadIdx.x, ty = threadIdx.y;
    tile[ty][tx] = in[((size_t)b*256 + c0 + ty) * HW + pos0 + tx];
    __syncthreads();
    float v = tile[tx][ty];
    __nv_bfloat16 h = __float2bfloat16(v);
    __nv_bfloat16 l = __float2bfloat16(v - __bfloat162float(h));
    size_t o = ((size_t)b*HW + pos0 + ty) * 256 + c0 + tx;
    oH[o] = h; oL[o] = l;
}

// pack reg weights: dst[L][tap][q][plane][oc][ch], c = q*64+ch, src OIHW
__global__ void pack_wB_k(const float* __restrict__ w0, const float* __restrict__ w1,
                          const float* __restrict__ w2, const float* __restrict__ w3,
                          __nv_bfloat16* __restrict__ dst, int n)
{
    int i = blockIdx.x * blockDim.x + threadIdx.x;
    if (i >= n) return;
    int L = i / 1179648;           // 9*4*2*256*64
    int r = i - L*1179648;
    int tap = r / 131072; r -= tap*131072;
    int q = r / 32768;  r -= q*32768;
    int plane = r / 16384; r -= plane*16384;
    int oc = r / 64;
    int ch = r - oc*64;
    int c = q*64 + ch;
    const float* w = (L==0)?w0:((L==1)?w1:((L==2)?w2:w3));
    float v = w[((size_t)oc*256 + c)*9 + tap];
    __nv_bfloat16 h = __float2bfloat16(v);
    dst[i] = plane ? __float2bfloat16(v - __bfloat162float(h)) : h;
}

// ===================== mma conv (cp.async pipelined) =====================
__device__ __forceinline__ unsigned smem_u32(const void* p) {
    unsigned a;
    asm("{ .reg .u64 t; cvta.to.shared.u64 t, %1; cvt.u32.u64 %0, t; }" : "=r"(a) : "l"(p));
    return a;
}
#define LDM_X4(R0,R1,R2,R3,ADDR) \
    asm volatile("ldmatrix.sync.aligned.m8n8.x4.shared.b16 {%0,%1,%2,%3}, [%4];" \
        : "=r"(R0),"=r"(R1),"=r"(R2),"=r"(R3) : "r"(ADDR))
#define MMA16816(D,A,B0,B1) \
    asm volatile("mma.sync.aligned.m16n8k16.row.col.f32.bf16.bf16.f32 " \
        "{%0,%1,%2,%3}, {%4,%5,%6,%7}, {%8,%9}, {%0,%1,%2,%3};" \
        : "+f"((D)[0]),"+f"((D)[1]),"+f"((D)[2]),"+f"((D)[3]) \
        : "r"((A)[0]),"r"((A)[1]),"r"((A)[2]),"r"((A)[3]),"r"(B0),"r"(B1))
#define CP16(DST, SRC, SZ) \
    asm volatile("cp.async.cg.shared.global [%0], [%1], 16, %2;" \
        :: "r"(DST), "l"(SRC), "r"(SZ) : "memory")
#define CP_COMMIT() asm volatile("cp.async.commit_group;" ::: "memory")

#define ROWB 144
#define PL   (128*ROWB)        // 18432
#define STAGE (4*PL)           // 73728 (Ahi,Alo,Bhi,Blo)
#define MMA2_SMEM (2*STAGE)    // 147456
#define EPL  (128*272)         // epilogue plane (34816)

template<int FINAL>
__global__ void __launch_bounds__(256, 1) conv_mma2_k(
    const __nv_bfloat16* __restrict__ aH, const __nv_bfloat16* __restrict__ aL,
    const __nv_bfloat16* __restrict__ wB,   // this layer: [36][2][256][64]
    const float* __restrict__ bias,
    float* __restrict__ outf,
    __nv_bfloat16* __restrict__ oH, __nv_bfloat16* __restrict__ oL,
    int klog, int HW)
{
    extern __shared__ __align__(16) unsigned char sm[];
    const unsigned smb = smem_u32(sm);
    const int t = threadIdx.x, lane = t & 31, wid = t >> 5;
    const int wm = wid & 3, wn = wid >> 2;
    const int m0 = blockIdx.x * 128, oc0 = blockIdx.y * 128;
    const int W = 1 << klog;

    // staging geometry: thread covers rows rb+32i (i=0..3), 16B chunk jj
    const int jj = t & 7, rb = t >> 3;
    int r_ab[4], r_ay[4], r_ax[4];
    #pragma unroll
    for (int i = 0; i < 4; i++) {
        int am = m0 + rb + 32*i;
        r_ab[i] = am >> (2*klog);
        int ap = am & (HW - 1);
        r_ay[i] = ap >> klog; r_ax[i] = ap & (W - 1);
    }

    float acc[2][8][4];
    #pragma unroll
    for (int mt = 0; mt < 2; mt++)
        #pragma unroll
        for (int nt = 0; nt < 8; nt++)
            #pragma unroll
            for (int k = 0; k < 4; k++) acc[mt][nt][k] = 0.f;

    const unsigned a_rowoff = (unsigned)(wm*32 + (lane & 15)) * ROWB + ((lane >> 4) << 4);
    const unsigned b_rowoff = (unsigned)(wn*64 + (((lane >> 4) & 1) << 3) + (lane & 7)) * ROWB
                            + (((lane >> 3) & 1) << 4);

    // ---- stage function ----
    auto stage = [&](int s) {
        int tap = s >> 2, q = s & 3, stg = s & 1;
        int tky = tap / 3, tkx = tap - 3*tky;
        unsigned ab_ = smb + stg*STAGE;
        unsigned bb_ = ab_ + 2*PL;
        #pragma unroll
        for (int i = 0; i < 4; i++) {
            int gy = r_ay[i] + tky - 1, gx = r_ax[i] + tkx - 1;
            unsigned sz = (((unsigned)gy < (unsigned)W) && ((unsigned)gx < (unsigned)W)) ? 16u : 0u;
            size_t off = ((size_t)r_ab[i]*HW + (size_t)((gy << klog) + gx)) * 256 + q*64 + jj*8;
            unsigned d = ab_ + (rb + 32*i)*ROWB + jj*16;
            CP16(d,      aH + off, sz);
            CP16(d + PL, aL + off, sz);
        }
        size_t sbase = (size_t)s * 32768 + (size_t)oc0 * 64;
        #pragma unroll
        for (int i = 0; i < 4; i++) {
            int row = rb + 32*i;
            size_t so = sbase + (size_t)row*64 + jj*8;
            unsigned d = bb_ + row*ROWB + jj*16;
            CP16(d,      wB + so,         16u);
            CP16(d + PL, wB + so + 16384, 16u);
        }
        CP_COMMIT();
    };

    stage(0);
    #pragma unroll 1
    for (int s = 0; s < 36; s++) {
        if (s < 35) stage(s + 1);
        if (s < 35) asm volatile("cp.async.wait_group 1;" ::: "memory");
        else        asm volatile("cp.async.wait_group 0;" ::: "memory");
        __syncthreads();

        unsigned abase = smb + (unsigned)(s & 1)*STAGE;
        unsigned bbase = abase + 2*PL;
        #pragma unroll
        for (int kc = 0; kc < 4; kc++) {
            unsigned ah[2][4], al[2][4];
            #pragma unroll
            for (int mt = 0; mt < 2; mt++) {
                unsigned aaddr = abase + a_rowoff + (unsigned)mt*16*ROWB + (unsigned)kc*32;
                LDM_X4(ah[mt][0], ah[mt][1], ah[mt][2], ah[mt][3], aaddr);
                LDM_X4(al[mt][0], al[mt][1], al[mt][2], al[mt][3], aaddr + PL);
            }
            #pragma unroll
            for (int p = 0; p < 4; p++) {
                unsigned bh[4], bl[4];
                unsigned baddr = bbase + b_rowoff + (unsigned)p*16*ROWB + (unsigned)kc*32;
                LDM_X4(bh[0], bh[1], bh[2], bh[3], baddr);
                LDM_X4(bl[0], bl[1], bl[2], bl[3], baddr + PL);
                #pragma unroll
                for (int mt = 0; mt < 2; mt++) {
                    MMA16816(acc[mt][2*p],   ah[mt], bh[0], bh[1]);
                    MMA16816(acc[mt][2*p],   ah[mt], bl[0], bl[1]);
                    MMA16816(acc[mt][2*p],   al[mt], bh[0], bh[1]);
                    MMA16816(acc[mt][2*p+1], ah[mt], bh[2], bh[3]);
                    MMA16816(acc[mt][2*p+1], ah[mt], bl[2], bl[3]);
                    MMA16816(acc[mt][2*p+1], al[mt], bh[2], bh[3]);
                }
            }
        }
        __syncthreads();
    }

    const int r = lane >> 2, c2 = (lane & 3) * 2;
    if (FINAL) {
        // NCHW fp32 (feeds scalar 36-OC head conv)
        #pragma unroll
        for (int mt = 0; mt < 2; mt++)
            #pragma unroll
            for (int nt = 0; nt < 8; nt++) {
                int oc = oc0 + wn*64 + nt*8 + c2;
                float b0 = bias[oc], b1 = bias[oc+1];
                #pragma unroll
                for (int half = 0; half < 2; half++) {
                    int pxr = m0 + wm*32 + mt*16 + r + half*8;
                    int bb = pxr >> (2*klog);
                    int pos = pxr & (HW - 1);
                    size_t o0 = ((size_t)bb*256 + oc) * HW + pos;
                    outf[o0]      = fmaxf(acc[mt][nt][half*2+0] + b0, 0.f);
                    outf[o0 + HW] = fmaxf(acc[mt][nt][half*2+1] + b1, 0.f);
                }
            }
    } else {
        // NHWC hi/lo planes via smem transpose (coalesced 256B bursts)
        unsigned char* smc = (unsigned char*)sm;
        #pragma unroll
        for (int mt = 0; mt < 2; mt++)
            #pragma unroll
            for (int nt = 0; nt < 8; nt++) {
                int ocl = wn*64 + nt*8 + c2;
                float b0 = bias[oc0+ocl], b1 = bias[oc0+ocl+1];
                #pragma unroll
                for (int half = 0; half < 2; half++) {
                    int pxl = wm*32 + mt*16 + r + half*8;
                    float v0 = fmaxf(acc[mt][nt][half*2+0] + b0, 0.f);
                    float v1 = fmaxf(acc[mt][nt][half*2+1] + b1, 0.f);
                    __nv_bfloat16 h0 = __float2bfloat16(v0);
                    __nv_bfloat16 h1 = __float2bfloat16(v1);
                    __nv_bfloat16 l0 = __float2bfloat16(v0 - __bfloat162float(h0));
                    __nv_bfloat16 l1 = __float2bfloat16(v1 - __bfloat162float(h1));
                    unsigned hw2 = (unsigned)__bfloat16_as_ushort(h0) | ((unsigned)__bfloat16_as_ushort(h1) << 16);
                    unsigned lw2 = (unsigned)__bfloat16_as_ushort(l0) | ((unsigned)__bfloat16_as_ushort(l1) << 16);
                    *(unsigned*)(smc + (size_t)pxl*272 + ocl*2)       = hw2;
                    *(unsigned*)(smc + EPL + (size_t)pxl*272 + ocl*2) = lw2;
                }
            }
        __syncthreads();
        #pragma unroll
        for (int i = 0; i < 16; i++) {
            int idx = i*256 + t;              // 4096 chunks of 16B
            int plane = idx >> 11;
            int rem = idx & 2047;
            int row = rem >> 4, j = rem & 15;
            uint4 v = *(uint4*)(smc + (size_t)plane*EPL + (size_t)row*272 + j*16);
            int pxg = m0 + row;
            int ab2 = pxg >> (2*klog);
            int pos = pxg & (HW - 1);
            size_t dstoff = ((size_t)ab2*HW + pos)*256 + oc0 + j*8;
            *(uint4*)((plane ? oL : oH) + dstoff) = v;
        }
    }
}

// ===================== epilogues =====================
__global__ void cls_reduce_k(const float* __restrict__ head,
                             float* __restrict__ scores, float* __restrict__ cls_id,
                             int H, int W, int Aoff, int Atot, int total)
{
    int idx = blockIdx.x * blockDim.x + threadIdx.x;
    if (idx >= total) return;
    int HW = H*W, pos = idx % HW, tmp = idx / HW, a = tmp % 9, b = tmp / 9;
    const float* p = head + ((size_t)b*720 + (size_t)a*80) * HW + pos;
    float best = p[0]; int bi = 0;
    #pragma unroll 4
    for (int k = 1; k < 80; k++) {
        float v = p[(size_t)k * HW];
        if (v > best) { best = v; bi = k; }
    }
    size_t o = (size_t)b*Atot + Aoff + (size_t)pos*9 + a;
    scores[o] = 1.f / (1.f + expf(-best));
    cls_id[o] = (float)bi;
}

__global__ void reg_decode_k(const float* __restrict__ head, float* __restrict__ boxes,
                             int H, int W, int stride, int Aoff, int Atot, int total)
{
    int idx = blockIdx.x * blockDim.x + threadIdx.x;
    if (idx >= total) return;
    int HW = H*W, pos = idx % HW, tmp = idx / HW, a = tmp % 9, b = tmp / 9;
    int x = pos % W, y = pos / W;
    const float* p = head + ((size_t)b*36 + (size_t)a*4) * HW + pos;
    float d0 = p[0], d1 = p[HW], d2 = p[2*(size_t)HW], d3 = p[3*(size_t)HW];
    float s = (float)stride;
    int ridx = a / 3, sidx = a - ridx*3;
    float ratio = (ridx == 0) ? 0.5f : ((ridx == 1) ? 1.f : 2.f);
    float scale = (sidx == 0) ? 1.f : ((sidx == 1) ? 1.2599210498948732f : 1.5874010519681994f);
    float aw = 4.f * s * scale * rsqrtf(ratio);
    float ah = aw * ratio;
    float cx = (x + 0.5f) * s, cy = (y + 0.5f) * s;
    float pcx = cx + d0 * 0.1f * aw;
    float pcy = cy + d1 * 0.1f * ah;
    float pw = expf(d2 * 0.2f) * aw;
    float ph = expf(d3 * 0.2f) * ah;
    float4 o4 = make_float4(pcx - 0.5f*pw, pcy - 0.5f*ph, pcx + 0.5f*pw, pcy + 0.5f*ph);
    size_t o = ((size_t)b*Atot + Aoff + (size_t)pos*9 + a);
    *(float4*)&boxes[o*4] = o4;
}

// ===========================================================================
extern "C" void kernel_launch(void* const* d_in, const int* in_sizes, int n_in,
                              void* d_out, int out_size)
{
    static const int HS[5] = {64, 32, 16, 8, 4};
    static const int KL[5] = {6, 5, 4, 3, 2};
    static const int SS[5] = {8, 16, 32, 64, 128};

    cudaFuncSetAttribute(conv_mma2_k<0>, cudaFuncAttributeMaxDynamicSharedMemorySize, MMA2_SMEM);
    cudaFuncSetAttribute(conv_mma2_k<1>, cudaFuncAttributeMaxDynamicSharedMemorySize, MMA2_SMEM);

    const float* feat[5];
    const float *cw[5], *cbv[5], *rw[5], *rbv[5];
    for (int l = 0; l < 5; l++) feat[l] = (const float*)d_in[l];
    for (int i = 0; i < 5; i++) {
        cw[i]  = (const float*)d_in[5  + 2*i];
        cbv[i] = (const float*)d_in[6  + 2*i];
        rw[i]  = (const float*)d_in[15 + 2*i];
        rbv[i] = (const float*)d_in[16 + 2*i];
    }
    int B = in_sizes[0] / (256 * 64 * 64);

    float *buf0, *buf1, *headb;
    __nv_bfloat16 *aH0, *aL0, *aH1, *aL1, *wB;
    cudaGetSymbolAddress((void**)&buf0, g_buf0);
    cudaGetSymbolAddress((void**)&buf1, g_buf1);
    cudaGetSymbolAddress((void**)&headb, g_head);
    cudaGetSymbolAddress((void**)&aH0, g_aH0);
    cudaGetSymbolAddress((void**)&aL0, g_aL0);
    cudaGetSymbolAddress((void**)&aH1, g_aH1);
    cudaGetSymbolAddress((void**)&aL1, g_aL1);
    cudaGetSymbolAddress((void**)&wB, g_wB);

    {   // pack reg weights (layers 0-3)
        int n = 4*1179648;
        pack_wB_k<<<(n + 255)/256, 256>>>(rw[0], rw[1], rw[2], rw[3], wB, n);
    }

    int Aoff[5], Atot = 0;
    for (int l = 0; l < 5; l++) { Aoff[l] = Atot; Atot += HS[l]*HS[l]*9; }

    float* out = (float*)d_out;
    float* out_scores = out;
    float* out_cls = out + (size_t)B * Atot;
    float* out_boxes = out + (size_t)2 * B * Atot;

    const size_t WLS = 1179648;   // per-layer weight stride (elems)

    for (int l = 0; l < 5; l++) {
        int H = HS[l], W = HS[l], HW = H*W;
        int tilesX = (W + TW - 1) / TW, tilesY = (H + TH - 1) / TH;
        dim3 grid(tilesX * tilesY, 4, B);
        dim3 gridCls(tilesX * tilesY, (720 + OCT - 1) / OCT, B);
        dim3 gridReg(tilesX * tilesY, 1, B);
        int total = B * 9 * HW;
        int rblk = (total + 255) / 256;

        // --- cls tower (scalar + Kahan; class_id argmax is tie-sensitive) ---
        const float* x = feat[l];
        for (int i = 0; i < 4; i++) {
            conv3x3_k<true><<<grid, 256>>>(x, cw[i], cbv[i], (i&1)?buf1:buf0, 256, H, W, tilesX, 1);
            x = (i&1)?buf1:buf0;
        }
        conv3x3_k<true><<<gridCls, 256>>>(x, cw[4], cbv[4], headb, 720, H, W, tilesX, 0);
        cls_reduce_k<<<rblk, 256>>>(headb, out_scores, out_cls, H, W, Aoff[l], Atot, total);

        // --- reg tower: layers 0-3 on pipelined mma ---
        dim3 gs(HW/16, 16, B);
        split_nhwc_k<<<gs, dim3(16,16)>>>(feat[l], aH0, aL0, HW);
        dim3 gt(B * HW / 128, 2, 1);
        conv_mma2_k<0><<<gt, 256, MMA2_SMEM>>>(aH0, aL0, wB + 0*WLS, rbv[0], nullptr, aH1, aL1, KL[l], HW);
        conv_mma2_k<0><<<gt, 256, MMA2_SMEM>>>(aH1, aL1, wB + 1*WLS, rbv[1], nullptr, aH0, aL0, KL[l], HW);
        conv_mma2_k<0><<<gt, 256, MMA2_SMEM>>>(aH0, aL0, wB + 2*WLS, rbv[2], nullptr, aH1, aL1, KL[l], HW);
        conv_mma2_k<1><<<gt, 256, MMA2_SMEM>>>(aH1, aL1, wB + 3*WLS, rbv[3], buf0, nullptr, nullptr, KL[l], HW);
        conv3x3_k<false><<<gridReg, 256>>>(buf0, rw[4], rbv[4], headb, 36, H, W, tilesX, 0);
        reg_decode_k<<<rblk, 256>>>(headb, out_boxes, H, W, SS[l], Aoff[l], Atot, total);
    }
    (void)n_in; (void)out_size;
}